// round 1
// baseline (speedup 1.0000x reference)
#include <cuda_runtime.h>

#define NROW 1024
#define THREADS 256
#define EPT 4  // NROW / THREADS

// ---- float <-> order-preserving u32 key ----
__device__ __forceinline__ unsigned f2s(float f) {
    unsigned u = __float_as_uint(f);
    return u ^ ((u & 0x80000000u) ? 0xFFFFFFFFu : 0x80000000u);
}
__device__ __forceinline__ float s2f(unsigned u) {
    u ^= ((u & 0x80000000u) ? 0x80000000u : 0xFFFFFFFFu);
    return __uint_as_float(u);
}

__device__ __forceinline__ float blockReduce(float v, float* buf) {
    __syncthreads();  // protect buf reuse across calls
    #pragma unroll
    for (int o = 16; o; o >>= 1) v += __shfl_down_sync(0xFFFFFFFFu, v, o);
    int w = threadIdx.x >> 5;
    if ((threadIdx.x & 31) == 0) buf[w] = v;
    __syncthreads();
    if (threadIdx.x < 32) {
        v = (threadIdx.x < (THREADS / 32)) ? buf[threadIdx.x] : 0.f;
        #pragma unroll
        for (int o = 4; o; o >>= 1) v += __shfl_down_sync(0xFFFFFFFFu, v, o);
        if (threadIdx.x == 0) buf[0] = v;
    }
    __syncthreads();
    return buf[0];
}

// Single-thread PAVA (non-increasing isotonic regression of y[i] = s[i] - (N-i)).
// Top-of-stack kept in registers; stack spill in shared. Writes pool means into
// ssum[0..depth) and pool start indices into sstart[0..depth).
__device__ void pava(const unsigned long long* key, float* ssum, float* scnt,
                     unsigned short* sstart, int* depth_out) {
    float cs, cc;
    int cst = 0, depth = 0;
    {
        unsigned long long kk = key[0];
        cs = s2f(~(unsigned)(kk >> 32)) - (float)NROW;
        cc = 1.f;
    }
    for (int i = 1; i < NROW; i++) {
        unsigned long long kk = key[i];
        float yi = s2f(~(unsigned)(kk >> 32)) - (float)(NROW - i);
        float s = yi, c = 1.f;
        int st = i;
        // merge while mean(new) > mean(cur)   <=>  s/c > cs/cc  (c,cc > 0)
        while (s * cc > cs * c) {
            s += cs; c += cc; st = cst;
            if (depth == 0) { cc = 0.f; break; }
            depth--;
            cs = ssum[depth]; cc = scnt[depth]; cst = (int)sstart[depth];
        }
        if (cc != 0.f) {
            ssum[depth] = cs; scnt[depth] = cc; sstart[depth] = (unsigned short)cst;
            depth++;
        }
        cs = s; cc = c; cst = st;
    }
    ssum[depth] = cs; scnt[depth] = cc; sstart[depth] = (unsigned short)cst;
    depth++;
    for (int p = 0; p < depth; p++) ssum[p] = ssum[p] / scnt[p];  // means in place
    *depth_out = depth;
}

__global__ __launch_bounds__(THREADS)
void spearman_kernel(const float* __restrict__ za, const float* __restrict__ zb,
                     const float* __restrict__ fcw, const float* __restrict__ fcb,
                     float* __restrict__ out) {
    __shared__ unsigned long long keyA[NROW];
    __shared__ unsigned long long keyB[NROW];
    __shared__ float ra[NROW];
    __shared__ float rb[NROW];
    __shared__ float ssumA[NROW], ssumB[NROW];
    __shared__ float scntA[NROW], scntB[NROW];
    __shared__ unsigned short sstartA[NROW], sstartB[NROW];
    __shared__ float red[32];
    __shared__ int depthA, depthB;

    const int row = blockIdx.x;
    const int tid = threadIdx.x;
    const float* A = za + (size_t)row * NROW;
    const float* B = zb + (size_t)row * NROW;

    // ---- build sortable keys ----
    #pragma unroll
    for (int r = 0; r < EPT; r++) {
        int j = tid + r * THREADS;
        keyA[j] = ((unsigned long long)(~f2s(A[j])) << 32) | (unsigned)j;
        keyB[j] = ((unsigned long long)(~f2s(B[j])) << 32) | (unsigned)j;
    }
    __syncthreads();

    // ---- bitonic sort (ascending u64 == descending value, stable idx) ----
    for (unsigned k = 2; k <= NROW; k <<= 1) {
        for (unsigned j = k >> 1; j > 0; j >>= 1) {
            #pragma unroll
            for (int r = 0; r < 2; r++) {
                unsigned t = tid + r * THREADS;  // 0..511
                unsigned i = ((t & ~(j - 1)) << 1) | (t & (j - 1));
                unsigned p = i | j;
                bool asc = ((i & k) == 0);
                unsigned long long x = keyA[i], y = keyA[p];
                if ((x > y) == asc) { keyA[i] = y; keyA[p] = x; }
                unsigned long long xb = keyB[i], yb = keyB[p];
                if ((xb > yb) == asc) { keyB[i] = yb; keyB[p] = xb; }
            }
            __syncthreads();
        }
    }

    // ---- two concurrent single-thread PAVAs (different warps) ----
    if (tid == 0)  pava(keyA, ssumA, scntA, sstartA, &depthA);
    if (tid == 32) pava(keyB, ssumB, scntB, sstartB, &depthB);
    __syncthreads();

    // ---- expand pools, compute out_sorted, scatter to original order ----
    const int dA = depthA, dB = depthB;
    float s1a = 0.f, s1b = 0.f;
    #pragma unroll
    for (int r = 0; r < EPT; r++) {
        int j = tid + r * THREADS;

        unsigned long long kk = keyA[j];
        float sv = s2f(~(unsigned)(kk >> 32));
        int idx = (int)((unsigned)kk & (NROW - 1));
        int lo = 0, hi = dA - 1;
        while (lo < hi) {
            int mid = (lo + hi + 1) >> 1;
            if ((int)sstartA[mid] <= j) lo = mid; else hi = mid - 1;
        }
        float osa = sv - ssumA[lo];
        ra[idx] = osa; s1a += osa;

        kk = keyB[j];
        sv = s2f(~(unsigned)(kk >> 32));
        idx = (int)((unsigned)kk & (NROW - 1));
        lo = 0; hi = dB - 1;
        while (lo < hi) {
            int mid = (lo + hi + 1) >> 1;
            if ((int)sstartB[mid] <= j) lo = mid; else hi = mid - 1;
        }
        float osb = sv - ssumB[lo];
        rb[idx] = osb; s1b += osb;
    }

    float ma = blockReduce(s1a, red) * (1.f / NROW);
    float mb = blockReduce(s1b, red) * (1.f / NROW);

    // ---- centered moments (two-pass avoids cancellation) ----
    float d = 0.f, va = 0.f, vb = 0.f;
    #pragma unroll
    for (int r = 0; r < EPT; r++) {
        int j = tid + r * THREADS;
        float x = ra[j] - ma;
        float y = rb[j] - mb;
        d += x * y; va += x * x; vb += y * y;
    }
    d  = blockReduce(d, red);
    va = blockReduce(va, red);
    vb = blockReduce(vb, red);

    if (tid == 0) {
        float corr = d * rsqrtf(va * vb);
        out[row] = fabsf(corr) * fcw[0] + fcb[0];
    }
}

extern "C" void kernel_launch(void* const* d_in, const int* in_sizes, int n_in,
                              void* d_out, int out_size) {
    const float* za  = (const float*)d_in[0];
    const float* zb  = (const float*)d_in[1];
    const float* fcw = (const float*)d_in[2];
    const float* fcb = (const float*)d_in[3];
    float* out = (float*)d_out;
    int B = in_sizes[0] / NROW;
    spearman_kernel<<<B, THREADS>>>(za, zb, fcw, fcb, out);
}

// round 4
// speedup vs baseline: 3.1362x; 3.1362x over previous
#include <cuda_runtime.h>

#define NROW 1024
#define THREADS 256
#define MAXP 256   // max tracked pools (Gaussian rows have ~1-10; guard on overflow)

// ---- float -> order-preserving u32, key = ~f2s(x) so ascending key == descending x ----
__device__ __forceinline__ unsigned f2s(float f) {
    unsigned u = __float_as_uint(f);
    return u ^ ((u & 0x80000000u) ? 0xFFFFFFFFu : 0x80000000u);
}
__device__ __forceinline__ float sdec(unsigned k) {   // inverse of (~f2s(x))
    unsigned u = ~k;
    u ^= ((u & 0x80000000u) ? 0x80000000u : 0xFFFFFFFFu);
    return __uint_as_float(u);
}
__device__ __forceinline__ void cxr(unsigned &a, unsigned &b, bool asc) {
    unsigned mn = min(a, b), mx = max(a, b);
    a = asc ? mn : mx;
    b = asc ? mx : mn;
}

struct SMem {
    unsigned kA[NROW];
    unsigned kB[NROW];
    float EA[NROW + 1];          // exclusive prefix sums of sorted values
    float EB[NROW + 1];
    unsigned bmA[32], bmB[32];   // boundary bitmasks, word q covers j in [32q,32q+32)
    unsigned short pstA[MAXP + 4], pstB[MAXP + 4];  // pool starts (+sentinel +pad)
    float pmA[MAXP], pmB[MAXP];  // pool means (sums during build)
    float redA[8], redB[8];
    float red5[8 * 5];
    int npA, npB;
};

// Tiny PAVA over candidate segments (serial, executed by one lane; segments are few).
__device__ void build_pools(const float* E, const unsigned* bm,
                            unsigned short* pst, float* pm, int* np_out) {
    int np = 0;
    int prev = 0;
    #pragma unroll 1
    for (int q = 0; q <= 32; q++) {
        unsigned m = (q < 32) ? bm[q] : 1u;  // q==32: sentinel => final segment ends at NROW
        while (m) {
            int l = __ffs(m) - 1;
            m &= m - 1;
            int end = (q < 32) ? ((q << 5) + l + 1) : NROW;
            if (end <= prev) continue;
            // segment [prev, end): y-sum = sum(s) - sum(1024 - j)
            int sw2 = (2049 - prev - end) * (end - prev);   // even, exact
            float s = (E[end] - E[prev]) - (float)(sw2 >> 1);
            int st = prev;
            // PAVA merge (strict violation, matching reference)
            while (np > 0) {
                float ctc = (float)(st - (int)pst[np - 1]);
                float cc  = (float)(end - st);
                if (s * ctc > pm[np - 1] * cc) { s += pm[np - 1]; st = (int)pst[np - 1]; np--; }
                else break;
            }
            if (np >= MAXP) { s += pm[np - 1]; st = (int)pst[np - 1]; np--; }  // unreachable guard
            pst[np] = (unsigned short)st;
            pm[np] = s;
            np++;
            prev = end;
            if (q == 32) break;
        }
    }
    pst[np] = (unsigned short)NROW;
    for (int p = 0; p < np; p++)
        pm[p] = pm[p] / (float)((int)pst[p + 1] - (int)pst[p]);
    *np_out = np;
}

__global__ __launch_bounds__(THREADS, 6)
void spearman_kernel(const float* __restrict__ za, const float* __restrict__ zb,
                     const float* __restrict__ fcw, const float* __restrict__ fcb,
                     float* __restrict__ out) {
    __shared__ SMem sm;

    const int row  = blockIdx.x;
    const int tid  = threadIdx.x;
    const int lane = tid & 31;
    const int w    = tid >> 5;

    const float4* A4 = (const float4*)(za + (size_t)row * NROW);
    const float4* B4 = (const float4*)(zb + (size_t)row * NROW);

    // ---- build keys ----
    {
        float4 xa = A4[tid];
        float4 xb = B4[tid];
        uint4 ka, kb;
        ka.x = ~f2s(xa.x); ka.y = ~f2s(xa.y); ka.z = ~f2s(xa.z); ka.w = ~f2s(xa.w);
        kb.x = ~f2s(xb.x); kb.y = ~f2s(xb.y); kb.z = ~f2s(xb.z); kb.w = ~f2s(xb.w);
        *(uint4*)&sm.kA[tid * 4] = ka;
        *(uint4*)&sm.kB[tid * 4] = kb;
    }
    __syncthreads();

    // ---- bitonic sort of 32-bit keys (ascending); j<=2 stages done in registers ----
    for (unsigned k = 2; k <= NROW; k <<= 1) {
        for (unsigned j = k >> 1; j >= 4; j >>= 1) {
            #pragma unroll
            for (int r = 0; r < 2; r++) {
                unsigned t = tid + r * THREADS;            // 0..511
                unsigned i = ((t & ~(j - 1)) << 1) | (t & (j - 1));
                unsigned p = i | j;
                bool asc = ((i & k) == 0);
                unsigned x = sm.kA[i], y = sm.kA[p];
                if ((x > y) == asc) { sm.kA[i] = y; sm.kA[p] = x; }
                unsigned xb = sm.kB[i], yb = sm.kB[p];
                if ((xb > yb) == asc) { sm.kB[i] = yb; sm.kB[p] = xb; }
            }
            __syncthreads();
        }
        // register pass: j=2 (k>=4) then j=1
        {
            const int base = tid * 4;
            uint4 q = *(uint4*)&sm.kA[base];
            if (k == 2) { cxr(q.x, q.y, true); cxr(q.z, q.w, false); }
            else {
                bool asc = ((base & k) == 0);
                cxr(q.x, q.z, asc); cxr(q.y, q.w, asc);
                cxr(q.x, q.y, asc); cxr(q.z, q.w, asc);
            }
            *(uint4*)&sm.kA[base] = q;
            uint4 p = *(uint4*)&sm.kB[base];
            if (k == 2) { cxr(p.x, p.y, true); cxr(p.z, p.w, false); }
            else {
                bool asc = ((base & k) == 0);
                cxr(p.x, p.z, asc); cxr(p.y, p.w, asc);
                cxr(p.x, p.y, asc); cxr(p.z, p.w, asc);
            }
            *(uint4*)&sm.kB[base] = p;
        }
        __syncthreads();
    }

    // ---- prefix scan of sorted values + boundary ballots ----
    float a0, a1, a2, a3, b0, b1, b2, b3, ca, cb, ia, ib;
    {
        uint4 qa = *(const uint4*)&sm.kA[tid * 4];
        uint4 qb = *(const uint4*)&sm.kB[tid * 4];
        a0 = sdec(qa.x); a1 = sdec(qa.y); a2 = sdec(qa.z); a3 = sdec(qa.w);
        b0 = sdec(qb.x); b1 = sdec(qb.y); b2 = sdec(qb.z); b3 = sdec(qb.w);
        ca = (a0 + a1) + (a2 + a3);
        cb = (b0 + b1) + (b2 + b3);
        ia = ca; ib = cb;
        #pragma unroll
        for (int o = 1; o < 32; o <<= 1) {
            float t = __shfl_up_sync(0xFFFFFFFFu, ia, o); if (lane >= o) ia += t;
            t = __shfl_up_sync(0xFFFFFFFFu, ib, o);       if (lane >= o) ib += t;
        }
        if (lane == 31) { sm.redA[w] = ia; sm.redB[w] = ib; }

        #pragma unroll
        for (int r = 0; r < 4; r++) {
            int j = tid + 256 * r;
            bool fA = false, fB = false;
            if (j < NROW - 1) {
                fA = (sdec(sm.kA[j]) - sdec(sm.kA[j + 1])) >= 1.0f;
                fB = (sdec(sm.kB[j]) - sdec(sm.kB[j + 1])) >= 1.0f;
            }
            unsigned mA = __ballot_sync(0xFFFFFFFFu, fA);
            unsigned mB = __ballot_sync(0xFFFFFFFFu, fB);
            if (lane == 0) { sm.bmA[r * 8 + w] = mA; sm.bmB[r * 8 + w] = mB; }
        }
    }
    __syncthreads();
    if (tid == 0) {
        float acc = 0.f;
        #pragma unroll
        for (int i = 0; i < 8; i++) { float t = sm.redA[i]; sm.redA[i] = acc; acc += t; }
        sm.EA[NROW] = acc;
        acc = 0.f;
        #pragma unroll
        for (int i = 0; i < 8; i++) { float t = sm.redB[i]; sm.redB[i] = acc; acc += t; }
        sm.EB[NROW] = acc;
    }
    __syncthreads();
    {
        float baseA = sm.redA[w] + (ia - ca);   // exclusive prefix before this chunk
        float baseB = sm.redB[w] + (ib - cb);
        int o = tid * 4;
        sm.EA[o + 0] = baseA;
        sm.EA[o + 1] = baseA + a0;
        sm.EA[o + 2] = baseA + a0 + a1;
        sm.EA[o + 3] = baseA + a0 + a1 + a2;
        sm.EB[o + 0] = baseB;
        sm.EB[o + 1] = baseB + b0;
        sm.EB[o + 2] = baseB + b0 + b1;
        sm.EB[o + 3] = baseB + b0 + b1 + b2;
    }
    __syncthreads();

    // ---- pool construction (tiny serial PAVA over segments) ----
    if (tid == 0)  build_pools(sm.EA, sm.bmA, sm.pstA, sm.pmA, &sm.npA);
    if (tid == 32) build_pools(sm.EB, sm.bmB, sm.pstB, sm.pmB, &sm.npB);
    __syncthreads();

    // pad pool-start arrays so epilogue binary search is branch-free over MAXP range
    {
        int npA = sm.npA, npB = sm.npB;
        if (tid > npA && tid <= MAXP) sm.pstA[tid] = 0xFFFFu;
        if (tid > npB && tid <= MAXP) sm.pstB[tid] = 0xFFFFu;
    }
    __syncthreads();

    // ---- epilogue: per original element, rank via binary search; accumulate moments ----
    // Pearson correlation is shift-invariant: subtract pm[0] from every pool mean so the
    // accumulated values are O(1) instead of O(512) -> no catastrophic cancellation.
    const float pm0A = sm.pmA[0];
    const float pm0B = sm.pmB[0];
    float sa = 0.f, sb = 0.f, saa = 0.f, sbb = 0.f, sab = 0.f;
    {
        float4 xa = A4[tid];
        float4 xb = B4[tid];
        float va[4] = {xa.x, xa.y, xa.z, xa.w};
        float vb[4] = {xb.x, xb.y, xb.z, xb.w};
        #pragma unroll
        for (int i = 0; i < 4; i++) {
            // --- A ---
            unsigned keyA = ~f2s(va[i]);
            unsigned pos = 0;
            #pragma unroll
            for (unsigned step = 512; step >= 1; step >>= 1)
                if (sm.kA[pos + step - 1] < keyA) pos += step;
            unsigned pp = 0;
            #pragma unroll
            for (unsigned step = 128; step >= 1; step >>= 1)
                if ((unsigned)sm.pstA[pp + step] <= pos) pp += step;
            float oA = va[i] - (sm.pmA[pp] - pm0A);
            // --- B ---
            unsigned keyB = ~f2s(vb[i]);
            pos = 0;
            #pragma unroll
            for (unsigned step = 512; step >= 1; step >>= 1)
                if (sm.kB[pos + step - 1] < keyB) pos += step;
            pp = 0;
            #pragma unroll
            for (unsigned step = 128; step >= 1; step >>= 1)
                if ((unsigned)sm.pstB[pp + step] <= pos) pp += step;
            float oB = vb[i] - (sm.pmB[pp] - pm0B);

            sa += oA; sb += oB;
            saa += oA * oA; sbb += oB * oB; sab += oA * oB;
        }
    }

    // ---- fused 5-way block reduction ----
    #pragma unroll
    for (int o = 16; o; o >>= 1) {
        sa  += __shfl_down_sync(0xFFFFFFFFu, sa, o);
        sb  += __shfl_down_sync(0xFFFFFFFFu, sb, o);
        saa += __shfl_down_sync(0xFFFFFFFFu, saa, o);
        sbb += __shfl_down_sync(0xFFFFFFFFu, sbb, o);
        sab += __shfl_down_sync(0xFFFFFFFFu, sab, o);
    }
    if (lane == 0) {
        sm.red5[w * 5 + 0] = sa;
        sm.red5[w * 5 + 1] = sb;
        sm.red5[w * 5 + 2] = saa;
        sm.red5[w * 5 + 3] = sbb;
        sm.red5[w * 5 + 4] = sab;
    }
    __syncthreads();
    if (tid == 0) {
        float t0 = 0.f, t1 = 0.f, t2 = 0.f, t3 = 0.f, t4 = 0.f;
        #pragma unroll
        for (int i = 0; i < 8; i++) {
            t0 += sm.red5[i * 5 + 0];
            t1 += sm.red5[i * 5 + 1];
            t2 += sm.red5[i * 5 + 2];
            t3 += sm.red5[i * 5 + 3];
            t4 += sm.red5[i * 5 + 4];
        }
        const float invn = 1.0f / (float)NROW;
        float num  = t4 - t0 * t1 * invn;
        float denA = t2 - t0 * t0 * invn;
        float denB = t3 - t1 * t1 * invn;
        float corr = num * rsqrtf(denA * denB);
        out[row] = fabsf(corr) * fcw[0] + fcb[0];
    }
}

extern "C" void kernel_launch(void* const* d_in, const int* in_sizes, int n_in,
                              void* d_out, int out_size) {
    const float* za  = (const float*)d_in[0];
    const float* zb  = (const float*)d_in[1];
    const float* fcw = (const float*)d_in[2];
    const float* fcb = (const float*)d_in[3];
    float* outp = (float*)d_out;
    int B = in_sizes[0] / NROW;
    spearman_kernel<<<B, THREADS>>>(za, zb, fcw, fcb, outp);
}

// round 5
// speedup vs baseline: 4.8653x; 1.5514x over previous
#include <cuda_runtime.h>

#define NROW 1024
#define THREADS 256
#define MAXP 256   // max tracked pools (Gaussian rows have ~1-10; guard on overflow)

// ---- float -> order-preserving u32, key = ~f2s(x) so ascending key == descending x ----
__device__ __forceinline__ unsigned f2s(float f) {
    unsigned u = __float_as_uint(f);
    return u ^ ((u & 0x80000000u) ? 0xFFFFFFFFu : 0x80000000u);
}
__device__ __forceinline__ float sdec(unsigned k) {   // inverse of (~f2s(x))
    unsigned u = ~k;
    u ^= ((u & 0x80000000u) ? 0x80000000u : 0xFFFFFFFFu);
    return __uint_as_float(u);
}
__device__ __forceinline__ void cxr(unsigned &a, unsigned &b, bool asc) {
    unsigned mn = min(a, b), mx = max(a, b);
    a = asc ? mn : mx;
    b = asc ? mx : mn;
}
__device__ __forceinline__ unsigned keepmm(unsigned v, unsigned p, bool keep_min) {
    return keep_min ? min(v, p) : max(v, p);
}

struct SMem {
    unsigned kA[NROW];
    unsigned kB[NROW];
    float EA[NROW + 1];          // exclusive prefix sums of sorted values
    float EB[NROW + 1];
    unsigned bmA[32], bmB[32];   // boundary bitmasks, word q covers j in [32q,32q+32)
    unsigned short pstA[MAXP + 4], pstB[MAXP + 4];  // pool starts (+sentinel +pad)
    float pmA[MAXP], pmB[MAXP];  // pool means (sums during build)
    float redA[8], redB[8];
    float red5[8 * 5];
    int npA, npB;
};

// Tiny PAVA over candidate segments (serial, executed by one lane; segments are few).
__device__ void build_pools(const float* E, const unsigned* bm,
                            unsigned short* pst, float* pm, int* np_out) {
    int np = 0;
    int prev = 0;
    #pragma unroll 1
    for (int q = 0; q <= 32; q++) {
        unsigned m = (q < 32) ? bm[q] : 1u;  // q==32: sentinel => final segment ends at NROW
        while (m) {
            int l = __ffs(m) - 1;
            m &= m - 1;
            int end = (q < 32) ? ((q << 5) + l + 1) : NROW;
            if (end <= prev) continue;
            // segment [prev, end): y-sum = sum(s) - sum(1024 - j)
            int sw2 = (2049 - prev - end) * (end - prev);   // even, exact
            float s = (E[end] - E[prev]) - (float)(sw2 >> 1);
            int st = prev;
            while (np > 0) {
                float ctc = (float)(st - (int)pst[np - 1]);
                float cc  = (float)(end - st);
                if (s * ctc > pm[np - 1] * cc) { s += pm[np - 1]; st = (int)pst[np - 1]; np--; }
                else break;
            }
            if (np >= MAXP) { s += pm[np - 1]; st = (int)pst[np - 1]; np--; }  // unreachable guard
            pst[np] = (unsigned short)st;
            pm[np] = s;
            np++;
            prev = end;
            if (q == 32) break;
        }
    }
    pst[np] = (unsigned short)NROW;
    for (int p = 0; p < np; p++)
        pm[p] = pm[p] / (float)((int)pst[p + 1] - (int)pst[p]);
    *np_out = np;
}

__global__ __launch_bounds__(THREADS, 5)
void spearman_kernel(const float* __restrict__ za, const float* __restrict__ zb,
                     const float* __restrict__ fcw, const float* __restrict__ fcb,
                     float* __restrict__ out) {
    __shared__ SMem sm;

    const int row  = blockIdx.x;
    const int tid  = threadIdx.x;
    const int lane = tid & 31;
    const int w    = tid >> 5;
    const int base = tid * 4;          // this thread's quad: elements [base, base+4)

    const float4* A4 = (const float4*)(za + (size_t)row * NROW);
    const float4* B4 = (const float4*)(zb + (size_t)row * NROW);

    // ---- build keys (register-resident) ----
    uint4 qa, qb;
    {
        float4 xa = A4[tid];
        float4 xb = B4[tid];
        qa.x = ~f2s(xa.x); qa.y = ~f2s(xa.y); qa.z = ~f2s(xa.z); qa.w = ~f2s(xa.w);
        qb.x = ~f2s(xb.x); qb.y = ~f2s(xb.y); qb.z = ~f2s(xb.z); qb.w = ~f2s(xb.w);
    }

    // ---- bitonic sort, ascending keys == descending values ----
    // idx = base + i. j in {1,2}: registers. j in {4..64}: shfl_xor (mask j/4).
    // j in {128,256,512}: smem quad exchange. Only 6 smem passes total.

    // k = 2 (pairs 0-1 asc, 2-3 desc within quad)
    cxr(qa.x, qa.y, true);  cxr(qa.z, qa.w, false);
    cxr(qb.x, qb.y, true);  cxr(qb.z, qb.w, false);

    #pragma unroll 1
    for (unsigned k = 4; k <= NROW; k <<= 1) {
        // --- smem passes: j >= 128 ---
        #pragma unroll 1
        for (unsigned j = (k >> 1); j >= 128; j >>= 1) {
            *(uint4*)&sm.kA[base] = qa;
            *(uint4*)&sm.kB[base] = qb;
            __syncthreads();
            uint4 pa = *(const uint4*)&sm.kA[base ^ j];
            uint4 pb = *(const uint4*)&sm.kB[base ^ j];
            bool low = ((unsigned)base & j) == 0;
            bool asc = (((unsigned)base & k) == 0);
            bool km  = (low == asc);
            qa.x = keepmm(qa.x, pa.x, km); qa.y = keepmm(qa.y, pa.y, km);
            qa.z = keepmm(qa.z, pa.z, km); qa.w = keepmm(qa.w, pa.w, km);
            qb.x = keepmm(qb.x, pb.x, km); qb.y = keepmm(qb.y, pb.y, km);
            qb.z = keepmm(qb.z, pb.z, km); qb.w = keepmm(qb.w, pb.w, km);
            __syncthreads();
        }
        // --- shfl passes: 4 <= j <= 64 ---
        {
            unsigned jmax = (k >> 1) > 64u ? 64u : (k >> 1);
            bool asc = (((unsigned)base & k) == 0);
            #pragma unroll 1
            for (unsigned j = jmax; j >= 4; j >>= 1) {
                unsigned m = j >> 2;          // lane xor mask
                bool low = ((unsigned)lane & m) == 0;
                bool km  = (low == asc);
                unsigned px = __shfl_xor_sync(0xFFFFFFFFu, qa.x, m);
                unsigned py = __shfl_xor_sync(0xFFFFFFFFu, qa.y, m);
                unsigned pz = __shfl_xor_sync(0xFFFFFFFFu, qa.z, m);
                unsigned pw = __shfl_xor_sync(0xFFFFFFFFu, qa.w, m);
                unsigned rx = __shfl_xor_sync(0xFFFFFFFFu, qb.x, m);
                unsigned ry = __shfl_xor_sync(0xFFFFFFFFu, qb.y, m);
                unsigned rz = __shfl_xor_sync(0xFFFFFFFFu, qb.z, m);
                unsigned rw = __shfl_xor_sync(0xFFFFFFFFu, qb.w, m);
                qa.x = keepmm(qa.x, px, km); qa.y = keepmm(qa.y, py, km);
                qa.z = keepmm(qa.z, pz, km); qa.w = keepmm(qa.w, pw, km);
                qb.x = keepmm(qb.x, rx, km); qb.y = keepmm(qb.y, ry, km);
                qb.z = keepmm(qb.z, rz, km); qb.w = keepmm(qb.w, rw, km);
            }
        }
        // --- register passes: j = 2 then j = 1 (same direction across quad for k>=4) ---
        {
            bool asc = (((unsigned)base & k) == 0);
            cxr(qa.x, qa.z, asc); cxr(qa.y, qa.w, asc);
            cxr(qa.x, qa.y, asc); cxr(qa.z, qa.w, asc);
            cxr(qb.x, qb.z, asc); cxr(qb.y, qb.w, asc);
            cxr(qb.x, qb.y, asc); cxr(qb.z, qb.w, asc);
        }
    }

    // ---- publish sorted keys for epilogue searches ----
    *(uint4*)&sm.kA[base] = qa;
    *(uint4*)&sm.kB[base] = qb;

    // ---- prefix scan of sorted values (from registers) + boundary ballots ----
    float a0 = sdec(qa.x), a1 = sdec(qa.y), a2 = sdec(qa.z), a3 = sdec(qa.w);
    float b0 = sdec(qb.x), b1 = sdec(qb.y), b2 = sdec(qb.z), b3 = sdec(qb.w);
    float ca = (a0 + a1) + (a2 + a3);
    float cb = (b0 + b1) + (b2 + b3);
    float ia = ca, ib = cb;
    #pragma unroll
    for (int o = 1; o < 32; o <<= 1) {
        float t = __shfl_up_sync(0xFFFFFFFFu, ia, o); if (lane >= o) ia += t;
        t = __shfl_up_sync(0xFFFFFFFFu, ib, o);       if (lane >= o) ib += t;
    }
    if (lane == 31) { sm.redA[w] = ia; sm.redB[w] = ib; }
    __syncthreads();   // keys + warp sums visible

    // boundary ballots (read neighbors from smem; word q covers j in [32q,32q+32))
    #pragma unroll
    for (int r = 0; r < 4; r++) {
        int j = tid + 256 * r;
        bool fA = false, fB = false;
        if (j < NROW - 1) {
            fA = (sdec(sm.kA[j]) - sdec(sm.kA[j + 1])) >= 1.0f;
            fB = (sdec(sm.kB[j]) - sdec(sm.kB[j + 1])) >= 1.0f;
        }
        unsigned mA = __ballot_sync(0xFFFFFFFFu, fA);
        unsigned mB = __ballot_sync(0xFFFFFFFFu, fB);
        if (lane == 0) { sm.bmA[r * 8 + w] = mA; sm.bmB[r * 8 + w] = mB; }
    }
    if (tid == 0) {
        float acc = 0.f;
        #pragma unroll
        for (int i = 0; i < 8; i++) { float t = sm.redA[i]; sm.redA[i] = acc; acc += t; }
        sm.EA[NROW] = acc;
        acc = 0.f;
        #pragma unroll
        for (int i = 0; i < 8; i++) { float t = sm.redB[i]; sm.redB[i] = acc; acc += t; }
        sm.EB[NROW] = acc;
    }
    __syncthreads();
    {
        float baseA = sm.redA[w] + (ia - ca);   // exclusive prefix before this quad
        float baseB = sm.redB[w] + (ib - cb);
        sm.EA[base + 0] = baseA;
        sm.EA[base + 1] = baseA + a0;
        sm.EA[base + 2] = baseA + a0 + a1;
        sm.EA[base + 3] = baseA + a0 + a1 + a2;
        sm.EB[base + 0] = baseB;
        sm.EB[base + 1] = baseB + b0;
        sm.EB[base + 2] = baseB + b0 + b1;
        sm.EB[base + 3] = baseB + b0 + b1 + b2;
    }
    __syncthreads();

    // ---- pool construction (tiny serial PAVA over segments) ----
    if (tid == 0)  build_pools(sm.EA, sm.bmA, sm.pstA, sm.pmA, &sm.npA);
    if (tid == 32) build_pools(sm.EB, sm.bmB, sm.pstB, sm.pmB, &sm.npB);
    __syncthreads();

    // pad pool-start arrays so epilogue binary search is branch-free over MAXP range
    {
        int npA = sm.npA, npB = sm.npB;
        if (tid > npA && tid <= MAXP) sm.pstA[tid] = 0xFFFFu;
        if (tid > npB && tid <= MAXP) sm.pstB[tid] = 0xFFFFu;
    }
    __syncthreads();

    // ---- epilogue: per original element, rank via binary search; accumulate moments ----
    // Pearson is shift-invariant: subtract pm[0] so accumulated values are O(1).
    const float pm0A = sm.pmA[0];
    const float pm0B = sm.pmB[0];
    float sa = 0.f, sb = 0.f, saa = 0.f, sbb = 0.f, sab = 0.f;
    {
        float4 xa = A4[tid];
        float4 xb = B4[tid];
        float va[4] = {xa.x, xa.y, xa.z, xa.w};
        float vb[4] = {xb.x, xb.y, xb.z, xb.w};
        #pragma unroll
        for (int i = 0; i < 4; i++) {
            // --- A ---
            unsigned keyA = ~f2s(va[i]);
            unsigned pos = 0;
            #pragma unroll
            for (unsigned step = 512; step >= 1; step >>= 1)
                if (sm.kA[pos + step - 1] < keyA) pos += step;
            unsigned pp = 0;
            #pragma unroll
            for (unsigned step = 128; step >= 1; step >>= 1)
                if ((unsigned)sm.pstA[pp + step] <= pos) pp += step;
            float oA = va[i] - (sm.pmA[pp] - pm0A);
            // --- B ---
            unsigned keyB = ~f2s(vb[i]);
            pos = 0;
            #pragma unroll
            for (unsigned step = 512; step >= 1; step >>= 1)
                if (sm.kB[pos + step - 1] < keyB) pos += step;
            pp = 0;
            #pragma unroll
            for (unsigned step = 128; step >= 1; step >>= 1)
                if ((unsigned)sm.pstB[pp + step] <= pos) pp += step;
            float oB = vb[i] - (sm.pmB[pp] - pm0B);

            sa += oA; sb += oB;
            saa += oA * oA; sbb += oB * oB; sab += oA * oB;
        }
    }

    // ---- fused 5-way block reduction ----
    #pragma unroll
    for (int o = 16; o; o >>= 1) {
        sa  += __shfl_down_sync(0xFFFFFFFFu, sa, o);
        sb  += __shfl_down_sync(0xFFFFFFFFu, sb, o);
        saa += __shfl_down_sync(0xFFFFFFFFu, saa, o);
        sbb += __shfl_down_sync(0xFFFFFFFFu, sbb, o);
        sab += __shfl_down_sync(0xFFFFFFFFu, sab, o);
    }
    if (lane == 0) {
        sm.red5[w * 5 + 0] = sa;
        sm.red5[w * 5 + 1] = sb;
        sm.red5[w * 5 + 2] = saa;
        sm.red5[w * 5 + 3] = sbb;
        sm.red5[w * 5 + 4] = sab;
    }
    __syncthreads();
    if (tid == 0) {
        float t0 = 0.f, t1 = 0.f, t2 = 0.f, t3 = 0.f, t4 = 0.f;
        #pragma unroll
        for (int i = 0; i < 8; i++) {
            t0 += sm.red5[i * 5 + 0];
            t1 += sm.red5[i * 5 + 1];
            t2 += sm.red5[i * 5 + 2];
            t3 += sm.red5[i * 5 + 3];
            t4 += sm.red5[i * 5 + 4];
        }
        const float invn = 1.0f / (float)NROW;
        float num  = t4 - t0 * t1 * invn;
        float denA = t2 - t0 * t0 * invn;
        float denB = t3 - t1 * t1 * invn;
        float corr = num * rsqrtf(denA * denB);
        out[row] = fabsf(corr) * fcw[0] + fcb[0];
    }
}

extern "C" void kernel_launch(void* const* d_in, const int* in_sizes, int n_in,
                              void* d_out, int out_size) {
    const float* za  = (const float*)d_in[0];
    const float* zb  = (const float*)d_in[1];
    const float* fcw = (const float*)d_in[2];
    const float* fcb = (const float*)d_in[3];
    float* outp = (float*)d_out;
    int B = in_sizes[0] / NROW;
    spearman_kernel<<<B, THREADS>>>(za, zb, fcw, fcb, outp);
}

// round 9
// speedup vs baseline: 7.9891x; 1.6421x over previous
#include <cuda_runtime.h>

#define NROW 1024
#define THREADS 256
#define MAXP 256   // max tracked pools (Gaussian rows have ~1-10; guard on overflow)

// ---- float -> order-preserving u32 ----
__device__ __forceinline__ unsigned f2s(float f) {
    unsigned u = __float_as_uint(f);
    return u ^ ((u & 0x80000000u) ? 0xFFFFFFFFu : 0x80000000u);
}
__device__ __forceinline__ void cxr(unsigned &a, unsigned &b, bool asc) {
    unsigned mn = min(a, b), mx = max(a, b);
    a = asc ? mn : mx;
    b = asc ? mx : mn;
}
__device__ __forceinline__ unsigned keepmm(unsigned v, unsigned p, bool keep_min) {
    return keep_min ? min(v, p) : max(v, p);
}

struct SMem {
    alignas(16) float vA[NROW];      // input values (original order) -> later o-values
    alignas(16) float vB[NROW];
    alignas(16) float EA[NROW + 4];  // exclusive prefix sums (sort key staging first)
    alignas(16) float EB[NROW + 4];  // padded to 16B multiple so EB base stays 16-aligned
    float sFA[THREADS];              // per-thread first sorted value (cross-thread gap)
    float sFB[THREADS];
    unsigned bmA[32], bmB[32];       // boundary bitmasks, word q covers j in [32q,32q+32)
    unsigned short pstA[MAXP + 4], pstB[MAXP + 4];  // pool starts (+sentinel +pad)
    float pmA[MAXP], pmB[MAXP];      // pool means (sums during build)
    float redA[8], redB[8];
    float red5[8 * 5];
    int npA, npB;
};

// Tiny PAVA over candidate segments (serial, executed by one lane; segments are few).
__device__ void build_pools(const float* E, const unsigned* bm,
                            unsigned short* pst, float* pm, int* np_out) {
    int np = 0;
    int prev = 0;
    #pragma unroll 1
    for (int q = 0; q <= 32; q++) {
        unsigned m = (q < 32) ? bm[q] : 1u;  // q==32: sentinel => final segment ends at NROW
        while (m) {
            int l = __ffs(m) - 1;
            m &= m - 1;
            int end = (q < 32) ? ((q << 5) + l + 1) : NROW;
            if (end <= prev) continue;
            // segment [prev, end): y-sum = sum(s) - sum(1024 - j)
            int sw2 = (2049 - prev - end) * (end - prev);   // even, exact
            float s = (E[end] - E[prev]) - (float)(sw2 >> 1);
            int st = prev;
            while (np > 0) {
                float ctc = (float)(st - (int)pst[np - 1]);
                float cc  = (float)(end - st);
                if (s * ctc > pm[np - 1] * cc) { s += pm[np - 1]; st = (int)pst[np - 1]; np--; }
                else break;
            }
            if (np >= MAXP) { s += pm[np - 1]; st = (int)pst[np - 1]; np--; }  // unreachable guard
            pst[np] = (unsigned short)st;
            pm[np] = s;
            np++;
            prev = end;
            if (q == 32) break;
        }
    }
    pst[np] = (unsigned short)NROW;
    for (int p = 0; p < np; p++)
        pm[p] = pm[p] / (float)((int)pst[p + 1] - (int)pst[p]);
    *np_out = np;
}

__global__ __launch_bounds__(THREADS, 5)
void spearman_kernel(const float* __restrict__ za, const float* __restrict__ zb,
                     const float* __restrict__ fcw, const float* __restrict__ fcb,
                     float* __restrict__ out) {
    __shared__ SMem sm;

    const int row  = blockIdx.x;
    const int tid  = threadIdx.x;
    const int lane = tid & 31;
    const int w    = tid >> 5;
    const int base = tid * 4;          // this thread's quad: sorted positions [base, base+4)

    const float4* A4 = (const float4*)(za + (size_t)row * NROW);
    const float4* B4 = (const float4*)(zb + (size_t)row * NROW);

    // ---- load inputs once; stash exact values; build idx-carrying keys ----
    uint4 qa, qb;
    {
        float4 xa = A4[tid];
        float4 xb = B4[tid];
        *(float4*)&sm.vA[base] = xa;
        *(float4*)&sm.vB[base] = xb;
        // key = (~f2s(x) & ~1023) | idx : ascending key == stable descending-value argsort
        qa.x = (~f2s(xa.x) & 0xFFFFFC00u) | (unsigned)(base + 0);
        qa.y = (~f2s(xa.y) & 0xFFFFFC00u) | (unsigned)(base + 1);
        qa.z = (~f2s(xa.z) & 0xFFFFFC00u) | (unsigned)(base + 2);
        qa.w = (~f2s(xa.w) & 0xFFFFFC00u) | (unsigned)(base + 3);
        qb.x = (~f2s(xb.x) & 0xFFFFFC00u) | (unsigned)(base + 0);
        qb.y = (~f2s(xb.y) & 0xFFFFFC00u) | (unsigned)(base + 1);
        qb.z = (~f2s(xb.z) & 0xFFFFFC00u) | (unsigned)(base + 2);
        qb.w = (~f2s(xb.w) & 0xFFFFFC00u) | (unsigned)(base + 3);
    }
    if (tid < 32) { sm.bmA[tid] = 0; sm.bmB[tid] = 0; }

    // ---- bitonic sort (ascending keys). j in {1,2}: registers; j in {4..64}: shfl;
    //      j in {128,256,512}: smem quad exchange staged through EA/EB space (free now).
    unsigned* stA = (unsigned*)sm.EA;
    unsigned* stB = (unsigned*)sm.EB;

    cxr(qa.x, qa.y, true);  cxr(qa.z, qa.w, false);
    cxr(qb.x, qb.y, true);  cxr(qb.z, qb.w, false);

    #pragma unroll 1
    for (unsigned k = 4; k <= NROW; k <<= 1) {
        #pragma unroll 1
        for (unsigned j = (k >> 1); j >= 128; j >>= 1) {
            __syncthreads();           // protect staging reuse across iterations
            *(uint4*)&stA[base] = qa;
            *(uint4*)&stB[base] = qb;
            __syncthreads();
            uint4 pa = *(const uint4*)&stA[base ^ j];
            uint4 pb = *(const uint4*)&stB[base ^ j];
            bool low = ((unsigned)base & j) == 0;
            bool asc = (((unsigned)base & k) == 0);
            bool km  = (low == asc);
            qa.x = keepmm(qa.x, pa.x, km); qa.y = keepmm(qa.y, pa.y, km);
            qa.z = keepmm(qa.z, pa.z, km); qa.w = keepmm(qa.w, pa.w, km);
            qb.x = keepmm(qb.x, pb.x, km); qb.y = keepmm(qb.y, pb.y, km);
            qb.z = keepmm(qb.z, pb.z, km); qb.w = keepmm(qb.w, pb.w, km);
        }
        {
            unsigned jmax = (k >> 1) > 64u ? 64u : (k >> 1);
            bool asc = (((unsigned)base & k) == 0);
            #pragma unroll 1
            for (unsigned j = jmax; j >= 4; j >>= 1) {
                unsigned m = j >> 2;
                bool low = ((unsigned)lane & m) == 0;
                bool km  = (low == asc);
                unsigned px = __shfl_xor_sync(0xFFFFFFFFu, qa.x, m);
                unsigned py = __shfl_xor_sync(0xFFFFFFFFu, qa.y, m);
                unsigned pz = __shfl_xor_sync(0xFFFFFFFFu, qa.z, m);
                unsigned pw = __shfl_xor_sync(0xFFFFFFFFu, qa.w, m);
                unsigned rx = __shfl_xor_sync(0xFFFFFFFFu, qb.x, m);
                unsigned ry = __shfl_xor_sync(0xFFFFFFFFu, qb.y, m);
                unsigned rz = __shfl_xor_sync(0xFFFFFFFFu, qb.z, m);
                unsigned rw = __shfl_xor_sync(0xFFFFFFFFu, qb.w, m);
                qa.x = keepmm(qa.x, px, km); qa.y = keepmm(qa.y, py, km);
                qa.z = keepmm(qa.z, pz, km); qa.w = keepmm(qa.w, pw, km);
                qb.x = keepmm(qb.x, rx, km); qb.y = keepmm(qb.y, ry, km);
                qb.z = keepmm(qb.z, rz, km); qb.w = keepmm(qb.w, rw, km);
            }
        }
        {
            bool asc = (((unsigned)base & k) == 0);
            cxr(qa.x, qa.z, asc); cxr(qa.y, qa.w, asc);
            cxr(qa.x, qa.y, asc); cxr(qa.z, qa.w, asc);
            cxr(qb.x, qb.z, asc); cxr(qb.y, qb.w, asc);
            cxr(qb.x, qb.y, asc); cxr(qb.z, qb.w, asc);
        }
    }
    __syncthreads();   // staging (EA/EB space) free; vA/vB stable since load

    // ---- gather exact sorted values via embedded indices ----
    const int iA0 = qa.x & 1023, iA1 = qa.y & 1023, iA2 = qa.z & 1023, iA3 = qa.w & 1023;
    const int iB0 = qb.x & 1023, iB1 = qb.y & 1023, iB2 = qb.z & 1023, iB3 = qb.w & 1023;
    const float a0 = sm.vA[iA0], a1 = sm.vA[iA1], a2 = sm.vA[iA2], a3 = sm.vA[iA3];
    const float b0 = sm.vB[iB0], b1 = sm.vB[iB1], b2 = sm.vB[iB2], b3 = sm.vB[iB3];

    // ---- prefix scan of sorted values ----
    float ca = (a0 + a1) + (a2 + a3);
    float cb = (b0 + b1) + (b2 + b3);
    float ia = ca, ib = cb;
    #pragma unroll
    for (int o = 1; o < 32; o <<= 1) {
        float t = __shfl_up_sync(0xFFFFFFFFu, ia, o); if (lane >= o) ia += t;
        t = __shfl_up_sync(0xFFFFFFFFu, ib, o);       if (lane >= o) ib += t;
    }
    if (lane == 31) { sm.redA[w] = ia; sm.redB[w] = ib; }
    sm.sFA[tid] = a0;
    sm.sFB[tid] = b0;
    __syncthreads();

    // ---- boundary candidates (exact gaps, conservative threshold) + bitmask ----
    {
        float nxtA = (tid < THREADS - 1) ? sm.sFA[tid + 1] : a3;
        float nxtB = (tid < THREADS - 1) ? sm.sFB[tid + 1] : b3;
        unsigned nibA = ((a0 - a1) >= 0.999f ? 1u : 0u) |
                        ((a1 - a2) >= 0.999f ? 2u : 0u) |
                        ((a2 - a3) >= 0.999f ? 4u : 0u) |
                        ((tid < THREADS - 1 && (a3 - nxtA) >= 0.999f) ? 8u : 0u);
        unsigned nibB = ((b0 - b1) >= 0.999f ? 1u : 0u) |
                        ((b1 - b2) >= 0.999f ? 2u : 0u) |
                        ((b2 - b3) >= 0.999f ? 4u : 0u) |
                        ((tid < THREADS - 1 && (b3 - nxtB) >= 0.999f) ? 8u : 0u);
        int sh = (tid & 7) * 4;
        if (nibA) atomicOr(&sm.bmA[tid >> 3], nibA << sh);
        if (nibB) atomicOr(&sm.bmB[tid >> 3], nibB << sh);
    }
    if (tid == 0) {
        float acc = 0.f;
        #pragma unroll
        for (int i = 0; i < 8; i++) { float t = sm.redA[i]; sm.redA[i] = acc; acc += t; }
        sm.EA[NROW] = acc;
        acc = 0.f;
        #pragma unroll
        for (int i = 0; i < 8; i++) { float t = sm.redB[i]; sm.redB[i] = acc; acc += t; }
        sm.EB[NROW] = acc;
    }
    __syncthreads();
    {
        float baseA = sm.redA[w] + (ia - ca);   // exclusive prefix before this quad
        float baseB = sm.redB[w] + (ib - cb);
        sm.EA[base + 0] = baseA;
        sm.EA[base + 1] = baseA + a0;
        sm.EA[base + 2] = baseA + a0 + a1;
        sm.EA[base + 3] = baseA + a0 + a1 + a2;
        sm.EB[base + 0] = baseB;
        sm.EB[base + 1] = baseB + b0;
        sm.EB[base + 2] = baseB + b0 + b1;
        sm.EB[base + 3] = baseB + b0 + b1 + b2;
    }
    __syncthreads();

    // ---- pool construction (tiny serial PAVA over candidate segments) ----
    if (tid == 0)  build_pools(sm.EA, sm.bmA, sm.pstA, sm.pmA, &sm.npA);
    if (tid == 32) build_pools(sm.EB, sm.bmB, sm.pstB, sm.pmB, &sm.npB);
    __syncthreads();
    {
        int npA = sm.npA, npB = sm.npB;
        if (tid > npA && tid <= MAXP) sm.pstA[tid] = 0xFFFFu;
        if (tid > npB && tid <= MAXP) sm.pstB[tid] = 0xFFFFu;
    }
    __syncthreads();

    // ---- compute o in sorted order; scatter to original positions (reuse vA/vB) ----
    // Pearson is shift-invariant: subtract pm[0] so values stay O(1).
    {
        const int npA = sm.npA;
        float oA[4];
        if (npA == 1) {            // pm[pp]-pm[0] == 0 for the single pool
            oA[0] = a0; oA[1] = a1; oA[2] = a2; oA[3] = a3;
        } else {
            const float pm0 = sm.pmA[0];
            unsigned pp = 0;
            #pragma unroll
            for (unsigned step = 128; step >= 1; step >>= 1)
                if ((unsigned)sm.pstA[pp + step] <= (unsigned)base) pp += step;
            float sv[4] = {a0, a1, a2, a3};
            #pragma unroll
            for (int i = 0; i < 4; i++) {
                while ((unsigned)sm.pstA[pp + 1] <= (unsigned)(base + i)) pp++;
                oA[i] = sv[i] - (sm.pmA[pp] - pm0);
            }
        }
        const int npB = sm.npB;
        float oB[4];
        if (npB == 1) {
            oB[0] = b0; oB[1] = b1; oB[2] = b2; oB[3] = b3;
        } else {
            const float pm0 = sm.pmB[0];
            unsigned pp = 0;
            #pragma unroll
            for (unsigned step = 128; step >= 1; step >>= 1)
                if ((unsigned)sm.pstB[pp + step] <= (unsigned)base) pp += step;
            float sv[4] = {b0, b1, b2, b3};
            #pragma unroll
            for (int i = 0; i < 4; i++) {
                while ((unsigned)sm.pstB[pp + 1] <= (unsigned)(base + i)) pp++;
                oB[i] = sv[i] - (sm.pmB[pp] - pm0);
            }
        }
        __syncthreads();           // all gathers (a*/b* reads) done before overwrite
        sm.vA[iA0] = oA[0]; sm.vA[iA1] = oA[1]; sm.vA[iA2] = oA[2]; sm.vA[iA3] = oA[3];
        sm.vB[iB0] = oB[0]; sm.vB[iB1] = oB[1]; sm.vB[iB2] = oB[2]; sm.vB[iB3] = oB[3];
    }
    __syncthreads();

    // ---- moments over aligned (A,B) pairs: contiguous vector reads ----
    float sa, sb, saa, sbb, sab;
    {
        float4 rA = *(const float4*)&sm.vA[base];
        float4 rB = *(const float4*)&sm.vB[base];
        sa  = (rA.x + rA.y) + (rA.z + rA.w);
        sb  = (rB.x + rB.y) + (rB.z + rB.w);
        saa = (rA.x * rA.x + rA.y * rA.y) + (rA.z * rA.z + rA.w * rA.w);
        sbb = (rB.x * rB.x + rB.y * rB.y) + (rB.z * rB.z + rB.w * rB.w);
        sab = (rA.x * rB.x + rA.y * rB.y) + (rA.z * rB.z + rA.w * rB.w);
    }
    #pragma unroll
    for (int o = 16; o; o >>= 1) {
        sa  += __shfl_down_sync(0xFFFFFFFFu, sa, o);
        sb  += __shfl_down_sync(0xFFFFFFFFu, sb, o);
        saa += __shfl_down_sync(0xFFFFFFFFu, saa, o);
        sbb += __shfl_down_sync(0xFFFFFFFFu, sbb, o);
        sab += __shfl_down_sync(0xFFFFFFFFu, sab, o);
    }
    if (lane == 0) {
        sm.red5[w * 5 + 0] = sa;
        sm.red5[w * 5 + 1] = sb;
        sm.red5[w * 5 + 2] = saa;
        sm.red5[w * 5 + 3] = sbb;
        sm.red5[w * 5 + 4] = sab;
    }
    __syncthreads();
    if (tid == 0) {
        float t0 = 0.f, t1 = 0.f, t2 = 0.f, t3 = 0.f, t4 = 0.f;
        #pragma unroll
        for (int i = 0; i < 8; i++) {
            t0 += sm.red5[i * 5 + 0];
            t1 += sm.red5[i * 5 + 1];
            t2 += sm.red5[i * 5 + 2];
            t3 += sm.red5[i * 5 + 3];
            t4 += sm.red5[i * 5 + 4];
        }
        const float invn = 1.0f / (float)NROW;
        float num  = t4 - t0 * t1 * invn;
        float denA = t2 - t0 * t0 * invn;
        float denB = t3 - t1 * t1 * invn;
        float corr = num * rsqrtf(denA * denB);
        out[row] = fabsf(corr) * fcw[0] + fcb[0];
    }
}

extern "C" void kernel_launch(void* const* d_in, const int* in_sizes, int n_in,
                              void* d_out, int out_size) {
    const float* za  = (const float*)d_in[0];
    const float* zb  = (const float*)d_in[1];
    const float* fcw = (const float*)d_in[2];
    const float* fcb = (const float*)d_in[3];
    float* outp = (float*)d_out;
    int B = in_sizes[0] / NROW;
    spearman_kernel<<<B, THREADS>>>(za, zb, fcw, fcb, outp);
}